// round 12
// baseline (speedup 1.0000x reference)
#include <cuda_runtime.h>
#include <cuda_bf16.h>

#define NB 8
#define NC 256
#define HW 16384            // 128*128
#define HW4 4096            // HW / 4
#define NK 64
#define SMOOTH 1e-6f

// Scratch (device globals: allocation-free per harness rules)
__device__ float g_score[NB * NC];
__device__ int   g_sel[NB * NK];

// ---------------------------------------------------------------------------
// Kernel A: per-channel uncertainty score (mean over H*W), fast-math version.
// Score is only consumed by the rank-sort; MUFU intrinsic error (~1e-9 in the
// channel mean after averaging) is far below adjacent score gaps (~8e-6).
// grid = NB*NC blocks, 256 threads; each thread reduces 64 elems (16 float4).
// At the dual floor: 3 MUFU/elem (~24us) == 134MB HBM (~23us).
// ---------------------------------------------------------------------------
__device__ __forceinline__ float unc(float v) {
    float ex = __expf(-v);
    float s  = __fdividef(1.0f, 1.0f + ex);
    return -s * __logf(s + SMOOTH);
}

__global__ void __launch_bounds__(256) score_kernel(const float* __restrict__ x) {
    const int bc  = blockIdx.x;                       // 0 .. NB*NC-1
    const int tid = threadIdx.x;
    const float4* xp = (const float4*)(x + (size_t)bc * HW);

    float sum = 0.0f;
#pragma unroll
    for (int i = 0; i < 16; i++) {
        float4 v = __ldcs(&xp[i * 256 + tid]);
        sum += unc(v.x);
        sum += unc(v.y);
        sum += unc(v.z);
        sum += unc(v.w);
    }

    // warp reduce
#pragma unroll
    for (int off = 16; off > 0; off >>= 1)
        sum += __shfl_down_sync(0xFFFFFFFFu, sum, off);

    __shared__ float warp_sums[8];
    if ((tid & 31) == 0) warp_sums[tid >> 5] = sum;
    __syncthreads();
    if (tid == 0) {
        float t = 0.0f;
#pragma unroll
        for (int wv = 0; wv < 8; wv++) t += warp_sums[wv];
        g_score[bc] = t * (1.0f / (float)HW);
    }
}

// ---------------------------------------------------------------------------
// Kernel B: per-batch rank-sort -> indices of the NK smallest scores,
// ascending (== jax.lax.top_k(-score): descending -score, ties -> lower idx).
// grid = NB blocks, 256 threads.
// ---------------------------------------------------------------------------
__global__ void __launch_bounds__(256) select_kernel() {
    const int b = blockIdx.x;
    const int t = threadIdx.x;
    __shared__ float s[NC];
    s[t] = g_score[b * NC + t];
    __syncthreads();

    const float my = s[t];
    int rank = 0;
#pragma unroll 8
    for (int j = 0; j < NC; j++) {
        float v = s[j];
        rank += (v < my) || (v == my && j < t);
    }
    if (rank < NK) g_sel[b * NK + rank] = t;
}

// ---------------------------------------------------------------------------
// Kernel C (fused attn + mul):
//  grid = (HW4/64, NB) = (64, 8) = 512 blocks; 256 threads.
//  Block owns a tile of 64 float4 positions (256 pixels) of batch b.
//  Phase 1: gather the 64 selected channels for this tile (default caching ->
//           lines stay L2-resident), K-loop split across 4 thread groups,
//           smem-reduce, sigmoid -> attn_s[64] in smem.
//  Phase 2: loop all 256 channels: out = x * attn  (streaming .cs loads/stores;
//           the 64 selected channels hit L2 from phase 1).
// ---------------------------------------------------------------------------
__global__ void __launch_bounds__(256) attn_mul_kernel(const float* __restrict__ x,
                                                       const float* __restrict__ w,
                                                       const float* __restrict__ bias,
                                                       float* __restrict__ out) {
    __shared__ int    sel[NK];
    __shared__ float  ws[NK];
    __shared__ float4 red[256];
    __shared__ float4 attn_s[64];

    const int b  = blockIdx.y;
    const int t  = threadIdx.x;
    const int pi = t & 63;          // position (float4) within tile
    const int kg = t >> 6;          // group 0..3 (k-split in ph1, c-split in ph2)
    if (t < NK) {
        sel[t] = g_sel[b * NK + t];
        ws[t]  = w[t];
    }
    __syncthreads();

    const int p4 = blockIdx.x * 64 + pi;
    const float4* xb = (const float4*)x + (size_t)b * NC * HW4;
    float4*       ob = (float4*)out     + (size_t)b * NC * HW4;

    // ---- Phase 1: attention for this tile ----
    float4 acc = make_float4(0.f, 0.f, 0.f, 0.f);
    const int k0 = kg * 16;
#pragma unroll
    for (int kk = 0; kk < 16; kk++) {
        const int k = k0 + kk;
        float4 v = xb[(size_t)sel[k] * HW4 + p4];   // default caching: keep in L2
        float wk = ws[k];
        acc.x += v.x * wk;
        acc.y += v.y * wk;
        acc.z += v.z * wk;
        acc.w += v.w * wk;
    }
    red[t] = acc;
    __syncthreads();

    if (kg == 0) {
        float4 a1 = red[t + 64], a2 = red[t + 128], a3 = red[t + 192];
        acc.x += a1.x + a2.x + a3.x;
        acc.y += a1.y + a2.y + a3.y;
        acc.z += a1.z + a2.z + a3.z;
        acc.w += a1.w + a2.w + a3.w;
        const float bb = bias[0];
        float4 a;
        a.x = 1.0f / (1.0f + expf(-(acc.x + bb)));
        a.y = 1.0f / (1.0f + expf(-(acc.y + bb)));
        a.z = 1.0f / (1.0f + expf(-(acc.z + bb)));
        a.w = 1.0f / (1.0f + expf(-(acc.w + bb)));
        attn_s[pi] = a;
    }
    __syncthreads();

    // ---- Phase 2: broadcast multiply over all 256 channels ----
    const float4 a = attn_s[pi];
#pragma unroll 8
    for (int ci = 0; ci < 64; ci++) {
        const int c = (kg << 6) + ci;
        const size_t off = (size_t)c * HW4 + p4;
        float4 v = __ldcs(&xb[off]);
        float4 o;
        o.x = v.x * a.x;
        o.y = v.y * a.y;
        o.z = v.z * a.z;
        o.w = v.w * a.w;
        __stcs(&ob[off], o);
    }
}

// ---------------------------------------------------------------------------
extern "C" void kernel_launch(void* const* d_in, const int* in_sizes, int n_in,
                              void* d_out, int out_size) {
    const float* x    = (const float*)d_in[0];   // [8,256,128,128] fp32
    const float* w    = (const float*)d_in[1];   // [64]
    const float* bias = (const float*)d_in[2];   // [1]
    float* out = (float*)d_out;

    score_kernel<<<NB * NC, 256>>>(x);
    select_kernel<<<NB, 256>>>();
    attn_mul_kernel<<<dim3(HW4 / 64, NB), 256>>>(x, w, bias, out);
}

// round 13
// speedup vs baseline: 1.0536x; 1.0536x over previous
#include <cuda_runtime.h>
#include <cuda_bf16.h>

#define NB 8
#define NC 256
#define HW 16384            // 128*128
#define HW4 4096            // HW / 4
#define NK 64
#define SMOOTH 1e-6f

// Scratch (device globals: allocation-free per harness rules)
__device__ float g_score[NB * NC];
__device__ int   g_sel[NB * NK];
__device__ float g_attn[NB * HW];

// ---------------------------------------------------------------------------
// Kernel A: per-channel uncertainty score (mean over H*W).
// Identity: -s*log(s+1e-6) = log(u)/u - 1e-6 + O(5e-13),  u = 1+e^{-x}.
// The -1e-6 is a constant shift (rank-invariant, dropped). log(u)/u =
// ln2 * lg2(u) * rcp(u): per element FMUL+EX2+FADD+RCP+LG2+FFMA only.
// Score feeds ONLY the rank-sort; approx-error fluctuation in the channel
// mean (~1e-9) is far below adjacent score gaps (~2e-5).
// grid = NB*NC blocks, 256 threads; each thread reduces 64 elems (16 float4).
// ---------------------------------------------------------------------------
__device__ __forceinline__ float unc2(float v) {
    float t = v * -1.44269504f;          // -x * log2(e)
    float ex; asm("ex2.approx.f32 %0, %1;" : "=f"(ex) : "f"(t));   // e^{-x}
    float u = 1.0f + ex;
    float r;  asm("rcp.approx.f32 %0, %1;" : "=f"(r)  : "f"(u));
    float l;  asm("lg2.approx.f32 %0, %1;" : "=f"(l)  : "f"(u));
    return l * r;                        // lg2(u)/u ; *ln2 folded into epilogue
}

__global__ void __launch_bounds__(256) score_kernel(const float* __restrict__ x) {
    const int bc  = blockIdx.x;                       // 0 .. NB*NC-1
    const int tid = threadIdx.x;
    const float4* xp = (const float4*)(x + (size_t)bc * HW);

    float sum = 0.0f;
#pragma unroll
    for (int i = 0; i < 16; i++) {
        float4 v = __ldcs(&xp[i * 256 + tid]);
        sum += unc2(v.x);
        sum += unc2(v.y);
        sum += unc2(v.z);
        sum += unc2(v.w);
    }

    // warp reduce
#pragma unroll
    for (int off = 16; off > 0; off >>= 1)
        sum += __shfl_down_sync(0xFFFFFFFFu, sum, off);

    __shared__ float warp_sums[8];
    if ((tid & 31) == 0) warp_sums[tid >> 5] = sum;
    __syncthreads();
    if (tid == 0) {
        float t = 0.0f;
#pragma unroll
        for (int wv = 0; wv < 8; wv++) t += warp_sums[wv];
        g_score[bc] = t * (0.69314718056f / (float)HW);   // * ln2 / HW
    }
}

// ---------------------------------------------------------------------------
// Kernel B: per-batch rank-sort -> indices of the NK smallest scores,
// ascending (== jax.lax.top_k(-score): descending -score, ties -> lower idx).
// grid = NB blocks, 256 threads.
// ---------------------------------------------------------------------------
__global__ void __launch_bounds__(256) select_kernel() {
    const int b = blockIdx.x;
    const int t = threadIdx.x;
    __shared__ float s[NC];
    s[t] = g_score[b * NC + t];
    __syncthreads();

    const float my = s[t];
    int rank = 0;
#pragma unroll 8
    for (int j = 0; j < NC; j++) {
        float v = s[j];
        rank += (v < my) || (v == my && j < t);
    }
    if (rank < NK) g_sel[b * NK + rank] = t;
}

// ---------------------------------------------------------------------------
// Kernel C: attn[b,p] = sigmoid( sum_k x[b, sel[b,k], p] * w[k] + bias ).
// grid = (HW4/64, NB) = (64, 8) = 512 blocks; 256 threads.
// Block covers 64 float4 positions; the K=64 loop is split across 4 thread
// groups of 16 k's each, partial sums reduced through shared memory.
// ---------------------------------------------------------------------------
__global__ void __launch_bounds__(256) attn_kernel(const float* __restrict__ x,
                                                   const float* __restrict__ w,
                                                   const float* __restrict__ bias) {
    __shared__ int    sel[NK];
    __shared__ float  ws[NK];
    __shared__ float4 red[256];
    const int b  = blockIdx.y;
    const int t  = threadIdx.x;
    const int pi = t & 63;          // position within block's 64-float4 tile
    const int kg = t >> 6;          // k-group 0..3
    if (t < NK) {
        sel[t] = g_sel[b * NK + t];
        ws[t]  = w[t];
    }
    __syncthreads();

    const int p4 = blockIdx.x * 64 + pi;
    const float4* xb = (const float4*)x + (size_t)b * NC * HW4;

    float4 acc = make_float4(0.f, 0.f, 0.f, 0.f);
    const int k0 = kg * 16;
#pragma unroll
    for (int kk = 0; kk < 16; kk++) {
        const int k = k0 + kk;
        float4 v = __ldcs(&xb[(size_t)sel[k] * HW4 + p4]);
        float wk = ws[k];
        acc.x += v.x * wk;
        acc.y += v.y * wk;
        acc.z += v.z * wk;
        acc.w += v.w * wk;
    }
    red[t] = acc;
    __syncthreads();

    if (kg == 0) {
        float4 a1 = red[t + 64], a2 = red[t + 128], a3 = red[t + 192];
        acc.x += a1.x + a2.x + a3.x;
        acc.y += a1.y + a2.y + a3.y;
        acc.z += a1.z + a2.z + a3.z;
        acc.w += a1.w + a2.w + a3.w;
        const float bb = bias[0];
        float4 a;
        a.x = 1.0f / (1.0f + expf(-(acc.x + bb)));
        a.y = 1.0f / (1.0f + expf(-(acc.y + bb)));
        a.z = 1.0f / (1.0f + expf(-(acc.z + bb)));
        a.w = 1.0f / (1.0f + expf(-(acc.w + bb)));
        ((float4*)g_attn)[b * HW4 + p4] = a;
    }
}

// ---------------------------------------------------------------------------
// Kernel D: out[b,c,p] = x[b,c,p] * attn[b,p].
// grid = 8192 blocks, 256 threads, four float4 each (ILP=4).
// x / out are single-use streams (__ldcs/__stcs); attn (512 KB) stays in L2.
// ---------------------------------------------------------------------------
__global__ void __launch_bounds__(256) mul_kernel(const float* __restrict__ x,
                                                  float* __restrict__ out) {
    const int base = blockIdx.x * 1024 + threadIdx.x;   // float4 index

    float4 v0 = __ldcs(((const float4*)x) + base);
    float4 v1 = __ldcs(((const float4*)x) + base + 256);
    float4 v2 = __ldcs(((const float4*)x) + base + 512);
    float4 v3 = __ldcs(((const float4*)x) + base + 768);

    int i0 = base, i1 = base + 256, i2 = base + 512, i3 = base + 768;
    float4 a0 = ((const float4*)g_attn)[((i0 >> 20) << 12) + (i0 & (HW4 - 1))];
    float4 a1 = ((const float4*)g_attn)[((i1 >> 20) << 12) + (i1 & (HW4 - 1))];
    float4 a2 = ((const float4*)g_attn)[((i2 >> 20) << 12) + (i2 & (HW4 - 1))];
    float4 a3 = ((const float4*)g_attn)[((i3 >> 20) << 12) + (i3 & (HW4 - 1))];

    float4 o0, o1, o2, o3;
    o0.x = v0.x * a0.x; o0.y = v0.y * a0.y; o0.z = v0.z * a0.z; o0.w = v0.w * a0.w;
    o1.x = v1.x * a1.x; o1.y = v1.y * a1.y; o1.z = v1.z * a1.z; o1.w = v1.w * a1.w;
    o2.x = v2.x * a2.x; o2.y = v2.y * a2.y; o2.z = v2.z * a2.z; o2.w = v2.w * a2.w;
    o3.x = v3.x * a3.x; o3.y = v3.y * a3.y; o3.z = v3.z * a3.z; o3.w = v3.w * a3.w;

    __stcs(((float4*)out) + i0, o0);
    __stcs(((float4*)out) + i1, o1);
    __stcs(((float4*)out) + i2, o2);
    __stcs(((float4*)out) + i3, o3);
}

// ---------------------------------------------------------------------------
extern "C" void kernel_launch(void* const* d_in, const int* in_sizes, int n_in,
                              void* d_out, int out_size) {
    const float* x    = (const float*)d_in[0];   // [8,256,128,128] fp32
    const float* w    = (const float*)d_in[1];   // [64]
    const float* bias = (const float*)d_in[2];   // [1]
    float* out = (float*)d_out;

    score_kernel<<<NB * NC, 256>>>(x);
    select_kernel<<<NB, 256>>>();
    attn_kernel<<<dim3(HW4 / 64, NB), 256>>>(x, w, bias);
    mul_kernel<<<(NB * NC * HW4) / 1024, 256>>>(x, out);
}

// round 14
// speedup vs baseline: 1.1078x; 1.0514x over previous
#include <cuda_runtime.h>
#include <cuda_bf16.h>

#define NB 8
#define NC 256
#define HW 16384            // 128*128
#define HW4 4096            // HW / 4
#define NK 64
#define SMOOTH 1e-6f

// Scratch (device globals: allocation-free per harness rules)
__device__ float g_score[NB * NC];
__device__ int   g_sel[NB * NK];
__device__ float g_attn[NB * HW];

// ---------------------------------------------------------------------------
// Kernel A: per-channel uncertainty score (mean over H*W).
// Identity: -s*log(s+1e-6) = log(u)/u - 1e-6 + O(5e-13),  u = 1+e^{-x}.
// The -1e-6 is a constant shift (rank-invariant, dropped). log(u)/u =
// ln2 * lg2(u) * rcp(u): per element FMUL+EX2+FADD+RCP+LG2+FFMA only.
// Loads use DEFAULT caching: x streams through L2 and the tail ~126 MB stays
// resident for the reverse-order consumers that follow.
// grid = NB*NC blocks, 256 threads; each thread reduces 64 elems (16 float4).
// ---------------------------------------------------------------------------
__device__ __forceinline__ float unc2(float v) {
    float t = v * -1.44269504f;          // -x * log2(e)
    float ex; asm("ex2.approx.f32 %0, %1;" : "=f"(ex) : "f"(t));   // e^{-x}
    float u = 1.0f + ex;
    float r;  asm("rcp.approx.f32 %0, %1;" : "=f"(r)  : "f"(u));
    float l;  asm("lg2.approx.f32 %0, %1;" : "=f"(l)  : "f"(u));
    return l * r;                        // lg2(u)/u ; *ln2 folded into epilogue
}

__global__ void __launch_bounds__(256) score_kernel(const float* __restrict__ x) {
    const int bc  = blockIdx.x;                       // 0 .. NB*NC-1
    const int tid = threadIdx.x;
    const float4* xp = (const float4*)(x + (size_t)bc * HW);

    float sum = 0.0f;
#pragma unroll
    for (int i = 0; i < 16; i++) {
        float4 v = xp[i * 256 + tid];                 // default caching -> L2
        sum += unc2(v.x);
        sum += unc2(v.y);
        sum += unc2(v.z);
        sum += unc2(v.w);
    }

    // warp reduce
#pragma unroll
    for (int off = 16; off > 0; off >>= 1)
        sum += __shfl_down_sync(0xFFFFFFFFu, sum, off);

    __shared__ float warp_sums[8];
    if ((tid & 31) == 0) warp_sums[tid >> 5] = sum;
    __syncthreads();
    if (tid == 0) {
        float t = 0.0f;
#pragma unroll
        for (int wv = 0; wv < 8; wv++) t += warp_sums[wv];
        g_score[bc] = t * (0.69314718056f / (float)HW);   // * ln2 / HW
    }
}

// ---------------------------------------------------------------------------
// Kernel B: per-batch rank-sort -> indices of the NK smallest scores,
// ascending (== jax.lax.top_k(-score): descending -score, ties -> lower idx).
// grid = NB blocks, 256 threads.
// ---------------------------------------------------------------------------
__global__ void __launch_bounds__(256) select_kernel() {
    const int b = blockIdx.x;
    const int t = threadIdx.x;
    __shared__ float s[NC];
    s[t] = g_score[b * NC + t];
    __syncthreads();

    const float my = s[t];
    int rank = 0;
#pragma unroll 8
    for (int j = 0; j < NC; j++) {
        float v = s[j];
        rank += (v < my) || (v == my && j < t);
    }
    if (rank < NK) g_sel[b * NK + rank] = t;
}

// ---------------------------------------------------------------------------
// Kernel C: attn[b,p] = sigmoid( sum_k x[b, sel[b,k], p] * w[k] + bias ).
// grid = (HW4/64, NB) = (64, 8) = 512 blocks; 256 threads.
// Default-cached loads: selected channels are partially L2-resident from the
// score pass and stay warm for the mul pass.
// ---------------------------------------------------------------------------
__global__ void __launch_bounds__(256) attn_kernel(const float* __restrict__ x,
                                                   const float* __restrict__ w,
                                                   const float* __restrict__ bias) {
    __shared__ int    sel[NK];
    __shared__ float  ws[NK];
    __shared__ float4 red[256];
    const int b  = blockIdx.y;
    const int t  = threadIdx.x;
    const int pi = t & 63;          // position within block's 64-float4 tile
    const int kg = t >> 6;          // k-group 0..3
    if (t < NK) {
        sel[t] = g_sel[b * NK + t];
        ws[t]  = w[t];
    }
    __syncthreads();

    const int p4 = blockIdx.x * 64 + pi;
    const float4* xb = (const float4*)x + (size_t)b * NC * HW4;

    float4 acc = make_float4(0.f, 0.f, 0.f, 0.f);
    const int k0 = kg * 16;
#pragma unroll
    for (int kk = 0; kk < 16; kk++) {
        const int k = k0 + kk;
        float4 v = xb[(size_t)sel[k] * HW4 + p4];     // default caching
        float wk = ws[k];
        acc.x += v.x * wk;
        acc.y += v.y * wk;
        acc.z += v.z * wk;
        acc.w += v.w * wk;
    }
    red[t] = acc;
    __syncthreads();

    if (kg == 0) {
        float4 a1 = red[t + 64], a2 = red[t + 128], a3 = red[t + 192];
        acc.x += a1.x + a2.x + a3.x;
        acc.y += a1.y + a2.y + a3.y;
        acc.z += a1.z + a2.z + a3.z;
        acc.w += a1.w + a2.w + a3.w;
        const float bb = bias[0];
        float4 a;
        a.x = 1.0f / (1.0f + expf(-(acc.x + bb)));
        a.y = 1.0f / (1.0f + expf(-(acc.y + bb)));
        a.z = 1.0f / (1.0f + expf(-(acc.z + bb)));
        a.w = 1.0f / (1.0f + expf(-(acc.w + bb)));
        ((float4*)g_attn)[b * HW4 + p4] = a;
    }
}

// ---------------------------------------------------------------------------
// Kernel D: out[b,c,p] = x[b,c,p] * attn[b,p].
// grid = 8192 blocks, 256 threads, four float4 each (ILP=4).
// REVERSE block order: the score pass streamed x ascending, so the tail of x
// is L2-resident; reading descending harvests those hits (anti-LRU order).
// x reads: default caching. out stores: __stcs (evict-first) so the write
// stream does not displace the not-yet-read portions of x.
// ---------------------------------------------------------------------------
__global__ void __launch_bounds__(256) mul_kernel(const float* __restrict__ x,
                                                  float* __restrict__ out) {
    const int rb   = (int)gridDim.x - 1 - (int)blockIdx.x;   // descending blocks
    const int base = rb * 1024 + threadIdx.x;                // float4 index

    float4 v0 = ((const float4*)x)[base];
    float4 v1 = ((const float4*)x)[base + 256];
    float4 v2 = ((const float4*)x)[base + 512];
    float4 v3 = ((const float4*)x)[base + 768];

    int i0 = base, i1 = base + 256, i2 = base + 512, i3 = base + 768;
    float4 a0 = ((const float4*)g_attn)[((i0 >> 20) << 12) + (i0 & (HW4 - 1))];
    float4 a1 = ((const float4*)g_attn)[((i1 >> 20) << 12) + (i1 & (HW4 - 1))];
    float4 a2 = ((const float4*)g_attn)[((i2 >> 20) << 12) + (i2 & (HW4 - 1))];
    float4 a3 = ((const float4*)g_attn)[((i3 >> 20) << 12) + (i3 & (HW4 - 1))];

    float4 o0, o1, o2, o3;
    o0.x = v0.x * a0.x; o0.y = v0.y * a0.y; o0.z = v0.z * a0.z; o0.w = v0.w * a0.w;
    o1.x = v1.x * a1.x; o1.y = v1.y * a1.y; o1.z = v1.z * a1.z; o1.w = v1.w * a1.w;
    o2.x = v2.x * a2.x; o2.y = v2.y * a2.y; o2.z = v2.z * a2.z; o2.w = v2.w * a2.w;
    o3.x = v3.x * a3.x; o3.y = v3.y * a3.y; o3.z = v3.z * a3.z; o3.w = v3.w * a3.w;

    __stcs(((float4*)out) + i0, o0);
    __stcs(((float4*)out) + i1, o1);
    __stcs(((float4*)out) + i2, o2);
    __stcs(((float4*)out) + i3, o3);
}

// ---------------------------------------------------------------------------
extern "C" void kernel_launch(void* const* d_in, const int* in_sizes, int n_in,
                              void* d_out, int out_size) {
    const float* x    = (const float*)d_in[0];   // [8,256,128,128] fp32
    const float* w    = (const float*)d_in[1];   // [64]
    const float* bias = (const float*)d_in[2];   // [1]
    float* out = (float*)d_out;

    score_kernel<<<NB * NC, 256>>>(x);
    select_kernel<<<NB, 256>>>();
    attn_kernel<<<dim3(HW4 / 64, NB), 256>>>(x, w, bias);
    mul_kernel<<<(NB * NC * HW4) / 1024, 256>>>(x, out);
}